// round 6
// baseline (speedup 1.0000x reference)
#include <cuda_runtime.h>
#include <cstdint>

#define NODES_MAX 100000
#define E_MAX     1600000

typedef unsigned long long ull;

// ---------------- device scratch (static, allocation-free) ----------------
__device__ float g_H[(size_t)NODES_MAX * 128];     // pre-aggregation h = (x*out_norm)@W
__device__ float g_AGG[(size_t)NODES_MAX * 128];   // aggregation result (128-wide layers)
__device__ float g_out_norm[NODES_MAX];
__device__ float g_in_norm[NODES_MAX];
__device__ int   g_odeg[NODES_MAX];
__device__ int   g_ideg[NODES_MAX];
__device__ int   g_row_beg[NODES_MAX];             // CSR segment start per dst node
__device__ int   g_fill[NODES_MAX];                // scatter cursors
__device__ int   g_csr_src[E_MAX];                 // src ids grouped by dst
__device__ int   g_alloc_ctr;                      // segment allocation cursor

// packed f32x2 fused multiply-add (sm_103a FFMA2; PTX-only)
#define FMA_F32X2(d, a, b, c) \
    asm("fma.rn.f32x2 %0, %1, %2, %3;" : "=l"(d) : "l"(a), "l"(b), "l"(c))

// ---------------- degree / norm ----------------
__global__ void k_init_deg(int n) {
    int i = blockIdx.x * blockDim.x + threadIdx.x;
    if (i < n) { g_odeg[i] = 1; g_ideg[i] = 1; }   // self-loop contributes 1 to each
    if (i == 0) g_alloc_ctr = 0;
}

__global__ void k_count_deg(const int* __restrict__ src, const int* __restrict__ dst, int E) {
    int i = blockIdx.x * blockDim.x + threadIdx.x;
    int st = gridDim.x * blockDim.x;
    for (; i < E; i += st) {
        atomicAdd(&g_odeg[src[i]], 1);
        atomicAdd(&g_ideg[dst[i]], 1);
    }
}

__global__ void k_norms(int n) {
    int i = blockIdx.x * blockDim.x + threadIdx.x;
    if (i < n) {
        g_out_norm[i] = rsqrtf((float)g_odeg[i]);
        g_in_norm[i]  = rsqrtf((float)g_ideg[i]);
    }
}

// ---------------- CSR segment allocation (order-free, fully parallel) ----------------
__global__ void __launch_bounds__(256)
k_alloc(int n) {
    __shared__ int warp_sums[8];
    __shared__ int block_base;
    int i    = blockIdx.x * 256 + threadIdx.x;
    int lane = threadIdx.x & 31;
    int wid  = threadIdx.x >> 5;
    int deg  = (i < n) ? (g_ideg[i] - 1) : 0;

    int v = deg;
#pragma unroll
    for (int off = 1; off < 32; off <<= 1) {
        int t = __shfl_up_sync(0xffffffffu, v, off);
        if (lane >= off) v += t;
    }
    if (lane == 31) warp_sums[wid] = v;
    __syncthreads();
    if (wid == 0) {
        int s = (lane < 8) ? warp_sums[lane] : 0;
#pragma unroll
        for (int off = 1; off < 8; off <<= 1) {
            int t = __shfl_up_sync(0xffffffffu, s, off);
            if (lane >= off) s += t;
        }
        if (lane < 8) warp_sums[lane] = s;
        if (lane == 7) block_base = atomicAdd(&g_alloc_ctr, s);
    }
    __syncthreads();
    int base = block_base + ((wid > 0) ? warp_sums[wid - 1] : 0) + (v - deg);
    if (i < n) { g_row_beg[i] = base; g_fill[i] = base; }
}

__global__ void k_scatter(const int* __restrict__ src, const int* __restrict__ dst, int E) {
    int i = blockIdx.x * blockDim.x + threadIdx.x;
    int st = gridDim.x * blockDim.x;
    for (; i < E; i += st) {
        int d = dst[i];
        int pos = atomicAdd(&g_fill[d], 1);
        g_csr_src[pos] = src[i];
    }
}

// ---------------- fused GEMM with packed f32x2 FMA (retuned) ----------------
// 64-row tiles; per-thread 8 rows x (DOUT/32) cols; acc = (even-k, odd-k) pairs.
// W staged pair-interleaved: wp[kp][c] = (W[2kp][c], W[2kp+1][c]).
//   MODE 0: X_eff[r][k] = X[r][k] * out_norm[r]
//   MODE 1: X_eff[r][k] = relu(g_AGG[r][k]*in_norm[r] + bprev[k]) * out_norm[r]
template <int DOUT, int MODE>
__global__ void __launch_bounds__(256, 2)
k_gemm2(const float* __restrict__ X, const float* __restrict__ W,
        const float* __restrict__ bprev, int n)
{
    constexpr int NCI  = DOUT / 32;   // cols per thread (stride-32 assignment)
    constexpr int ROWS = 64;          // rows per block
    constexpr int XSS  = 134;         // xs row stride in floats (even for LDS.64)

    extern __shared__ float sm[];
    ull*   wp = (ull*)sm;             // [64][DOUT] packed k-pairs
    float* xs = sm + 64 * DOUT * 2;   // [ROWS][XSS]

    const int t    = threadIdx.x;
    const int row0 = blockIdx.x * ROWS;

    // stage W pair-interleaved
    {
        float2* wp2 = (float2*)wp;
        for (int i = t; i < 64 * DOUT; i += 256) {
            int kp = i / DOUT, c = i - kp * DOUT;
            wp2[i] = make_float2(W[(2 * kp) * DOUT + c], W[(2 * kp + 1) * DOUT + c]);
        }
    }

    // stage X tile (previous layer's epilogue fused here)
    for (int i = t; i < ROWS * 32; i += 256) {
        int r  = i >> 5;
        int k4 = i & 31;
        int row = row0 + r;
        float4 v = make_float4(0.f, 0.f, 0.f, 0.f);
        if (row < n) {
            if (MODE == 0) {
                float on = g_out_norm[row];
                v = ((const float4*)X)[(size_t)row * 32 + k4];
                v.x *= on; v.y *= on; v.z *= on; v.w *= on;
            } else {
                float inn = g_in_norm[row];
                float on  = g_out_norm[row];
                float4 a  = ((const float4*)g_AGG)[(size_t)row * 32 + k4];
                float4 bb = ((const float4*)bprev)[k4];
                v.x = fmaxf(fmaf(a.x, inn, bb.x), 0.f) * on;
                v.y = fmaxf(fmaf(a.y, inn, bb.y), 0.f) * on;
                v.z = fmaxf(fmaf(a.z, inn, bb.z), 0.f) * on;
                v.w = fmaxf(fmaf(a.w, inn, bb.w), 0.f) * on;
            }
        }
        float2* p = (float2*)(xs + r * XSS + (k4 << 2));
        p[0] = make_float2(v.x, v.y);
        p[1] = make_float2(v.z, v.w);
    }
    __syncthreads();

    const int tx = t & 31;            // column base: cols tx + 32*ci
    const int rg = t >> 5;            // row group [0,8): rows rg*8 .. rg*8+7
    const float* xrow = xs + rg * 8 * XSS;
    const ull*   wpt  = wp + tx;

    ull acc[8][NCI];
#pragma unroll
    for (int r = 0; r < 8; r++)
#pragma unroll
        for (int ci = 0; ci < NCI; ci++) acc[r][ci] = 0ull;

#pragma unroll 4
    for (int kp = 0; kp < 64; kp++) {
        ull xv[8];
#pragma unroll
        for (int r = 0; r < 8; r++)
            xv[r] = *(const ull*)(xrow + r * XSS + kp * 2);
        ull wv[NCI];
#pragma unroll
        for (int ci = 0; ci < NCI; ci++)
            wv[ci] = wpt[kp * DOUT + 32 * ci];
#pragma unroll
        for (int r = 0; r < 8; r++)
#pragma unroll
            for (int ci = 0; ci < NCI; ci++)
                FMA_F32X2(acc[r][ci], xv[r], wv[ci], acc[r][ci]);
    }

    // horizontal add (even-k + odd-k lanes) and store
#pragma unroll
    for (int r = 0; r < 8; r++) {
        int row = row0 + rg * 8 + r;
        if (row < n) {
#pragma unroll
            for (int ci = 0; ci < NCI; ci++) {
                ull u = acc[r][ci];
                float lo = __uint_as_float((unsigned)(u & 0xffffffffull));
                float hi = __uint_as_float((unsigned)(u >> 32));
                g_H[(size_t)row * DOUT + tx + 32 * ci] = lo + hi;
            }
        }
    }
}

// ---------------- CSR gather-reduce aggregation ----------------
__global__ void __launch_bounds__(256)
k_agg128(int n) {
    int w    = (blockIdx.x * blockDim.x + threadIdx.x) >> 5;
    int lane = threadIdx.x & 31;
    if (w >= n) return;
    const float4* H4 = (const float4*)g_H;
    int beg = g_row_beg[w];
    int end = beg + g_ideg[w] - 1;
    float4 acc = H4[(size_t)w * 32 + lane];   // self-loop
    int j = beg;
    for (; j + 1 < end; j += 2) {
        int s0 = __ldg(&g_csr_src[j]);
        int s1 = __ldg(&g_csr_src[j + 1]);
        float4 v0 = H4[(size_t)s0 * 32 + lane];
        float4 v1 = H4[(size_t)s1 * 32 + lane];
        acc.x += v0.x; acc.y += v0.y; acc.z += v0.z; acc.w += v0.w;
        acc.x += v1.x; acc.y += v1.y; acc.z += v1.z; acc.w += v1.w;
    }
    if (j < end) {
        int s0 = __ldg(&g_csr_src[j]);
        float4 v0 = H4[(size_t)s0 * 32 + lane];
        acc.x += v0.x; acc.y += v0.y; acc.z += v0.z; acc.w += v0.w;
    }
    ((float4*)g_AGG)[(size_t)w * 32 + lane] = acc;
}

// 64-wide, final layer: half-warp per dst node; fuses out = acc*in_norm + b3.
__global__ void __launch_bounds__(256)
k_agg64_final(const float* __restrict__ b3, float* __restrict__ out, int n) {
    int gt   = blockIdx.x * blockDim.x + threadIdx.x;
    int lane = gt & 31;
    int w    = gt >> 5;
    int sub  = lane >> 4;
    int l16  = lane & 15;
    int node = w * 2 + sub;
    if (node >= n) return;
    const float4* H4 = (const float4*)g_H;
    int beg = g_row_beg[node];
    int end = beg + g_ideg[node] - 1;
    float4 acc = H4[(size_t)node * 16 + l16];  // self-loop
    int j = beg;
    for (; j + 1 < end; j += 2) {
        int s0 = __ldg(&g_csr_src[j]);
        int s1 = __ldg(&g_csr_src[j + 1]);
        float4 v0 = H4[(size_t)s0 * 16 + l16];
        float4 v1 = H4[(size_t)s1 * 16 + l16];
        acc.x += v0.x; acc.y += v0.y; acc.z += v0.z; acc.w += v0.w;
        acc.x += v1.x; acc.y += v1.y; acc.z += v1.z; acc.w += v1.w;
    }
    if (j < end) {
        int s0 = __ldg(&g_csr_src[j]);
        float4 v0 = H4[(size_t)s0 * 16 + l16];
        acc.x += v0.x; acc.y += v0.y; acc.z += v0.z; acc.w += v0.w;
    }
    float inn = g_in_norm[node];
    float4 bb = ((const float4*)b3)[l16];
    float4 o;
    o.x = fmaf(acc.x, inn, bb.x);
    o.y = fmaf(acc.y, inn, bb.y);
    o.z = fmaf(acc.z, inn, bb.z);
    o.w = fmaf(acc.w, inn, bb.w);
    ((float4*)out)[(size_t)node * 16 + l16] = o;
}

// ---------------- launcher ----------------
extern "C" void kernel_launch(void* const* d_in, const int* in_sizes, int n_in,
                              void* d_out, int out_size)
{
    const float* feat = (const float*)d_in[0];
    const int*   src  = (const int*)d_in[1];
    const int*   dst  = (const int*)d_in[2];
    const float* W1   = (const float*)d_in[3];
    const float* b1   = (const float*)d_in[4];
    const float* W2   = (const float*)d_in[5];
    const float* b2   = (const float*)d_in[6];
    const float* W3   = (const float*)d_in[7];
    const float* b3   = (const float*)d_in[8];
    float*       out  = (float*)d_out;

    const int n = in_sizes[0] / 128;   // 100000
    const int E = in_sizes[1];         // 1600000

    const int smem128 = 64 * 128 * 8 + 64 * 134 * 4;   // wp 64KB + xs 33.5KB = 99,840 B
    const int smem64  = 64 * 64 * 8 + 64 * 134 * 4;    // 67,072 B
    cudaFuncSetAttribute((const void*)k_gemm2<128, 0>,
                         cudaFuncAttributeMaxDynamicSharedMemorySize, smem128);
    cudaFuncSetAttribute((const void*)k_gemm2<128, 1>,
                         cudaFuncAttributeMaxDynamicSharedMemorySize, smem128);
    cudaFuncSetAttribute((const void*)k_gemm2<64, 1>,
                         cudaFuncAttributeMaxDynamicSharedMemorySize, smem64);

    // degrees + norms (self-loop via init=1)
    k_init_deg<<<(n + 255) / 256, 256>>>(n);
    k_count_deg<<<1024, 256>>>(src, dst, E);
    k_norms<<<(n + 255) / 256, 256>>>(n);

    // CSR build: parallel segment allocation + scatter (reused by all 3 layers)
    k_alloc<<<(n + 255) / 256, 256>>>(n);
    k_scatter<<<1024, 256>>>(src, dst, E);

    const int gblocks = (n + 63) / 64;

    // layer 1
    k_gemm2<128, 0><<<gblocks, 256, smem128>>>(feat, W1, nullptr, n);
    k_agg128<<<(n * 32 + 255) / 256, 256>>>(n);

    // layer 2
    k_gemm2<128, 1><<<gblocks, 256, smem128>>>(nullptr, W2, b1, n);
    k_agg128<<<(n * 32 + 255) / 256, 256>>>(n);

    // layer 3 (64-wide) + fused final epilogue straight to d_out
    k_gemm2<64, 1><<<gblocks, 256, smem64>>>(nullptr, W3, b2, n);
    k_agg64_final<<<(n * 16 + 255) / 256, 256>>>(b3, out, n);
}

// round 7
// speedup vs baseline: 1.2711x; 1.2711x over previous
#include <cuda_runtime.h>
#include <cstdint>

#define NODES_MAX 100000
#define E_MAX     1600000

// ---------------- device scratch (static, allocation-free) ----------------
__device__ float g_HA[(size_t)NODES_MAX * 128];    // ping
__device__ float g_HB[(size_t)NODES_MAX * 128];    // pong
__device__ float g_out_norm[NODES_MAX];
__device__ float g_in_norm[NODES_MAX];
__device__ int   g_odeg[NODES_MAX];
__device__ int   g_ideg[NODES_MAX];
__device__ int   g_row_beg[NODES_MAX];             // CSR segment start per dst node
__device__ int   g_fill[NODES_MAX];                // scatter cursors
__device__ int   g_csr_src[E_MAX];                 // src ids grouped by dst
__device__ int   g_alloc_ctr;                      // segment allocation cursor

// ---------------- degree / norm ----------------
__global__ void k_init_deg(int n) {
    int i = blockIdx.x * blockDim.x + threadIdx.x;
    if (i < n) { g_odeg[i] = 1; g_ideg[i] = 1; }   // self-loop contributes 1 to each
    if (i == 0) g_alloc_ctr = 0;
}

__global__ void k_count_deg(const int* __restrict__ src, const int* __restrict__ dst, int E) {
    int i = blockIdx.x * blockDim.x + threadIdx.x;
    int st = gridDim.x * blockDim.x;
    for (; i < E; i += st) {
        atomicAdd(&g_odeg[src[i]], 1);
        atomicAdd(&g_ideg[dst[i]], 1);
    }
}

__global__ void k_norms(int n) {
    int i = blockIdx.x * blockDim.x + threadIdx.x;
    if (i < n) {
        g_out_norm[i] = rsqrtf((float)g_odeg[i]);
        g_in_norm[i]  = rsqrtf((float)g_ideg[i]);
    }
}

// ---------------- CSR segment allocation (order-free, fully parallel) ----------------
__global__ void __launch_bounds__(256)
k_alloc(int n) {
    __shared__ int warp_sums[8];
    __shared__ int block_base;
    int i    = blockIdx.x * 256 + threadIdx.x;
    int lane = threadIdx.x & 31;
    int wid  = threadIdx.x >> 5;
    int deg  = (i < n) ? (g_ideg[i] - 1) : 0;

    int v = deg;
#pragma unroll
    for (int off = 1; off < 32; off <<= 1) {
        int t = __shfl_up_sync(0xffffffffu, v, off);
        if (lane >= off) v += t;
    }
    if (lane == 31) warp_sums[wid] = v;
    __syncthreads();
    if (wid == 0) {
        int s = (lane < 8) ? warp_sums[lane] : 0;
#pragma unroll
        for (int off = 1; off < 8; off <<= 1) {
            int t = __shfl_up_sync(0xffffffffu, s, off);
            if (lane >= off) s += t;
        }
        if (lane < 8) warp_sums[lane] = s;
        if (lane == 7) block_base = atomicAdd(&g_alloc_ctr, s);
    }
    __syncthreads();
    int base = block_base + ((wid > 0) ? warp_sums[wid - 1] : 0) + (v - deg);
    if (i < n) { g_row_beg[i] = base; g_fill[i] = base; }
}

__global__ void k_scatter(const int* __restrict__ src, const int* __restrict__ dst, int E) {
    int i = blockIdx.x * blockDim.x + threadIdx.x;
    int st = gridDim.x * blockDim.x;
    for (; i < E; i += st) {
        int d = dst[i];
        int pos = atomicAdd(&g_fill[d], 1);
        g_csr_src[pos] = src[i];
    }
}

// ---------------- layer-1 GEMM (R4-proven FFMA kernel, MODE 0 only) ----------------
// g_HA = (feat * out_norm) @ W1
__global__ void __launch_bounds__(256)
k_gemm1(const float* __restrict__ X, const float* __restrict__ W, int n)
{
    constexpr int DOUT = 128;
    constexpr int CG   = DOUT / 4;    // 32 float4 column groups
    constexpr int ROWS = 64;
    constexpr int XSS  = 136;

    extern __shared__ float sm[];
    float* ws = sm;                   // [128][DOUT]
    float* xs = sm + 128 * DOUT;      // [ROWS][XSS]

    const int t    = threadIdx.x;
    const int row0 = blockIdx.x * ROWS;

    {
        const float4* W4  = (const float4*)W;
        float4*       ws4 = (float4*)ws;
        for (int i = t; i < 128 * CG; i += 256) ws4[i] = W4[i];
    }

    for (int i = t; i < ROWS * 32; i += 256) {
        int r  = i >> 5;
        int k4 = i & 31;
        int row = row0 + r;
        float4 v = make_float4(0.f, 0.f, 0.f, 0.f);
        if (row < n) {
            float on = g_out_norm[row];
            v = ((const float4*)X)[(size_t)row * 32 + k4];
            v.x *= on; v.y *= on; v.z *= on; v.w *= on;
        }
        float* p = &xs[r * XSS + (k4 << 2)];
        p[0] = v.x; p[1] = v.y; p[2] = v.z; p[3] = v.w;
    }
    __syncthreads();

    const int tx = t % CG;
    const int ty = t / CG;
    float acc[8][4];
#pragma unroll
    for (int r = 0; r < 8; r++) { acc[r][0] = acc[r][1] = acc[r][2] = acc[r][3] = 0.f; }

    const float*  xrow = xs + ty * 8 * XSS;
    const float4* ws4  = (const float4*)ws;

#pragma unroll 4
    for (int k4 = 0; k4 < 32; k4++) {
        float4 w0 = ws4[(k4 * 4 + 0) * CG + tx];
        float4 w1 = ws4[(k4 * 4 + 1) * CG + tx];
        float4 w2 = ws4[(k4 * 4 + 2) * CG + tx];
        float4 w3 = ws4[(k4 * 4 + 3) * CG + tx];
#pragma unroll
        for (int r = 0; r < 8; r++) {
            float4 xv = *(const float4*)&xrow[r * XSS + k4 * 4];
            acc[r][0] = fmaf(xv.x, w0.x, acc[r][0]);
            acc[r][1] = fmaf(xv.x, w0.y, acc[r][1]);
            acc[r][2] = fmaf(xv.x, w0.z, acc[r][2]);
            acc[r][3] = fmaf(xv.x, w0.w, acc[r][3]);
            acc[r][0] = fmaf(xv.y, w1.x, acc[r][0]);
            acc[r][1] = fmaf(xv.y, w1.y, acc[r][1]);
            acc[r][2] = fmaf(xv.y, w1.z, acc[r][2]);
            acc[r][3] = fmaf(xv.y, w1.w, acc[r][3]);
            acc[r][0] = fmaf(xv.z, w2.x, acc[r][0]);
            acc[r][1] = fmaf(xv.z, w2.y, acc[r][1]);
            acc[r][2] = fmaf(xv.z, w2.z, acc[r][2]);
            acc[r][3] = fmaf(xv.z, w2.w, acc[r][3]);
            acc[r][0] = fmaf(xv.w, w3.x, acc[r][0]);
            acc[r][1] = fmaf(xv.w, w3.y, acc[r][1]);
            acc[r][2] = fmaf(xv.w, w3.z, acc[r][2]);
            acc[r][3] = fmaf(xv.w, w3.w, acc[r][3]);
        }
    }

#pragma unroll
    for (int r = 0; r < 8; r++) {
        int row = row0 + ty * 8 + r;
        if (row < n) {
            float4 v = make_float4(acc[r][0], acc[r][1], acc[r][2], acc[r][3]);
            ((float4*)g_HA)[(size_t)row * CG + tx] = v;
        }
    }
}

// ---------------- fused aggregate + GEMM ----------------
// X-staging performs the CSR gather-reduce over the PREVIOUS layer's H (Hin),
// then applies relu(acc*in_norm + bprev)*out_norm, then the standard FFMA GEMM.
// AB=0: Hin=g_HA, Hout=g_HB.  AB=1: Hin=g_HB, Hout=g_HA.
template <int DOUT, int AB>
__global__ void __launch_bounds__(256)
k_gemm_agg(const float* __restrict__ W, const float* __restrict__ bprev, int n)
{
    constexpr int CG   = DOUT / 4;    // float4 column groups
    constexpr int TY   = 256 / CG;    // row groups
    constexpr int ROWS = TY * 8;      // 64 (DOUT=128) / 128 (DOUT=64)
    constexpr int XSS  = 136;

    const float* Hin  = AB ? g_HB : g_HA;
    float*       Hout = AB ? g_HA : g_HB;

    extern __shared__ float sm[];
    float* ws = sm;                   // [128][DOUT]
    float* xs = sm + 128 * DOUT;      // [ROWS][XSS]

    const int t    = threadIdx.x;
    const int lane = t & 31;
    const int wid  = t >> 5;
    const int row0 = blockIdx.x * ROWS;

    // stage W
    {
        const float4* W4  = (const float4*)W;
        float4*       ws4 = (float4*)ws;
        for (int i = t; i < 128 * CG; i += 256) ws4[i] = W4[i];
    }

    // stage X: warp-per-row CSR gather-reduce + epilogue
    {
        const float4* H4 = (const float4*)Hin;
        const float4  bb = ((const float4*)bprev)[lane];   // input width always 128
        for (int r = wid; r < ROWS; r += 8) {
            int row = row0 + r;
            float4 v = make_float4(0.f, 0.f, 0.f, 0.f);
            if (row < n) {
                int beg = g_row_beg[row];
                int end = beg + g_ideg[row] - 1;
                float4 acc = H4[(size_t)row * 32 + lane];  // self-loop
                int j = beg;
                for (; j + 1 < end; j += 2) {
                    int s0 = __ldg(&g_csr_src[j]);
                    int s1 = __ldg(&g_csr_src[j + 1]);
                    float4 v0 = H4[(size_t)s0 * 32 + lane];
                    float4 v1 = H4[(size_t)s1 * 32 + lane];
                    acc.x += v0.x; acc.y += v0.y; acc.z += v0.z; acc.w += v0.w;
                    acc.x += v1.x; acc.y += v1.y; acc.z += v1.z; acc.w += v1.w;
                }
                if (j < end) {
                    int s0 = __ldg(&g_csr_src[j]);
                    float4 v0 = H4[(size_t)s0 * 32 + lane];
                    acc.x += v0.x; acc.y += v0.y; acc.z += v0.z; acc.w += v0.w;
                }
                float inn = g_in_norm[row];
                float on  = g_out_norm[row];
                v.x = fmaxf(fmaf(acc.x, inn, bb.x), 0.f) * on;
                v.y = fmaxf(fmaf(acc.y, inn, bb.y), 0.f) * on;
                v.z = fmaxf(fmaf(acc.z, inn, bb.z), 0.f) * on;
                v.w = fmaxf(fmaf(acc.w, inn, bb.w), 0.f) * on;
            }
            *(float4*)(xs + r * XSS + lane * 4) = v;
        }
    }
    __syncthreads();

    const int tx = t % CG;
    const int ty = t / CG;
    float acc[8][4];
#pragma unroll
    for (int r = 0; r < 8; r++) { acc[r][0] = acc[r][1] = acc[r][2] = acc[r][3] = 0.f; }

    const float*  xrow = xs + ty * 8 * XSS;
    const float4* ws4  = (const float4*)ws;

#pragma unroll 4
    for (int k4 = 0; k4 < 32; k4++) {
        float4 w0 = ws4[(k4 * 4 + 0) * CG + tx];
        float4 w1 = ws4[(k4 * 4 + 1) * CG + tx];
        float4 w2 = ws4[(k4 * 4 + 2) * CG + tx];
        float4 w3 = ws4[(k4 * 4 + 3) * CG + tx];
#pragma unroll
        for (int r = 0; r < 8; r++) {
            float4 xv = *(const float4*)&xrow[r * XSS + k4 * 4];
            acc[r][0] = fmaf(xv.x, w0.x, acc[r][0]);
            acc[r][1] = fmaf(xv.x, w0.y, acc[r][1]);
            acc[r][2] = fmaf(xv.x, w0.z, acc[r][2]);
            acc[r][3] = fmaf(xv.x, w0.w, acc[r][3]);
            acc[r][0] = fmaf(xv.y, w1.x, acc[r][0]);
            acc[r][1] = fmaf(xv.y, w1.y, acc[r][1]);
            acc[r][2] = fmaf(xv.y, w1.z, acc[r][2]);
            acc[r][3] = fmaf(xv.y, w1.w, acc[r][3]);
            acc[r][0] = fmaf(xv.z, w2.x, acc[r][0]);
            acc[r][1] = fmaf(xv.z, w2.y, acc[r][1]);
            acc[r][2] = fmaf(xv.z, w2.z, acc[r][2]);
            acc[r][3] = fmaf(xv.z, w2.w, acc[r][3]);
            acc[r][0] = fmaf(xv.w, w3.x, acc[r][0]);
            acc[r][1] = fmaf(xv.w, w3.y, acc[r][1]);
            acc[r][2] = fmaf(xv.w, w3.z, acc[r][2]);
            acc[r][3] = fmaf(xv.w, w3.w, acc[r][3]);
        }
    }

#pragma unroll
    for (int r = 0; r < 8; r++) {
        int row = row0 + ty * 8 + r;
        if (row < n) {
            float4 v = make_float4(acc[r][0], acc[r][1], acc[r][2], acc[r][3]);
            ((float4*)Hout)[(size_t)row * CG + tx] = v;
        }
    }
}

// ---------------- final layer aggregation: out = (gather H3)*in_norm + b3 ----------------
// H3 lives 64-wide in g_HA. Half-warp per dst node.
__global__ void __launch_bounds__(256)
k_agg64_final(const float* __restrict__ b3, float* __restrict__ out, int n) {
    int gt   = blockIdx.x * blockDim.x + threadIdx.x;
    int lane = gt & 31;
    int w    = gt >> 5;
    int sub  = lane >> 4;
    int l16  = lane & 15;
    int node = w * 2 + sub;
    if (node >= n) return;
    const float4* H4 = (const float4*)g_HA;
    int beg = g_row_beg[node];
    int end = beg + g_ideg[node] - 1;
    float4 acc = H4[(size_t)node * 16 + l16];  // self-loop
    int j = beg;
    for (; j + 1 < end; j += 2) {
        int s0 = __ldg(&g_csr_src[j]);
        int s1 = __ldg(&g_csr_src[j + 1]);
        float4 v0 = H4[(size_t)s0 * 16 + l16];
        float4 v1 = H4[(size_t)s1 * 16 + l16];
        acc.x += v0.x; acc.y += v0.y; acc.z += v0.z; acc.w += v0.w;
        acc.x += v1.x; acc.y += v1.y; acc.z += v1.z; acc.w += v1.w;
    }
    if (j < end) {
        int s0 = __ldg(&g_csr_src[j]);
        float4 v0 = H4[(size_t)s0 * 16 + l16];
        acc.x += v0.x; acc.y += v0.y; acc.z += v0.z; acc.w += v0.w;
    }
    float inn = g_in_norm[node];
    float4 bb = ((const float4*)b3)[l16];
    float4 o;
    o.x = fmaf(acc.x, inn, bb.x);
    o.y = fmaf(acc.y, inn, bb.y);
    o.z = fmaf(acc.z, inn, bb.z);
    o.w = fmaf(acc.w, inn, bb.w);
    ((float4*)out)[(size_t)node * 16 + l16] = o;
}

// ---------------- launcher ----------------
extern "C" void kernel_launch(void* const* d_in, const int* in_sizes, int n_in,
                              void* d_out, int out_size)
{
    const float* feat = (const float*)d_in[0];
    const int*   src  = (const int*)d_in[1];
    const int*   dst  = (const int*)d_in[2];
    const float* W1   = (const float*)d_in[3];
    const float* b1   = (const float*)d_in[4];
    const float* W2   = (const float*)d_in[5];
    const float* b2   = (const float*)d_in[6];
    const float* W3   = (const float*)d_in[7];
    const float* b3   = (const float*)d_in[8];
    float*       out  = (float*)d_out;

    const int n = in_sizes[0] / 128;   // 100000
    const int E = in_sizes[1];         // 1600000

    const int smem128 = (128 * 128 + 64 * 136) * (int)sizeof(float);    // 100,352 B
    const int smem64  = (128 * 64 + 128 * 136) * (int)sizeof(float);    // 102,400 B
    cudaFuncSetAttribute((const void*)k_gemm1,
                         cudaFuncAttributeMaxDynamicSharedMemorySize, smem128);
    cudaFuncSetAttribute((const void*)k_gemm_agg<128, 0>,
                         cudaFuncAttributeMaxDynamicSharedMemorySize, smem128);
    cudaFuncSetAttribute((const void*)k_gemm_agg<64, 1>,
                         cudaFuncAttributeMaxDynamicSharedMemorySize, smem64);

    // degrees + norms (self-loop via init=1)
    k_init_deg<<<(n + 255) / 256, 256>>>(n);
    k_count_deg<<<1024, 256>>>(src, dst, E);
    k_norms<<<(n + 255) / 256, 256>>>(n);

    // CSR build: parallel segment allocation + scatter (reused by all 3 layers)
    k_alloc<<<(n + 255) / 256, 256>>>(n);
    k_scatter<<<1024, 256>>>(src, dst, E);

    // layer 1: HA = (feat*out_norm)@W1
    k_gemm1<<<(n + 63) / 64, 256, smem128>>>(feat, W1, n);

    // layer 2 fused: HB = relu((gather HA)*in_norm + b1)*out_norm @ W2
    k_gemm_agg<128, 0><<<(n + 63) / 64, 256, smem128>>>(W2, b1, n);

    // layer 3 fused (64-wide): HA = relu((gather HB)*in_norm + b2)*out_norm @ W3
    k_gemm_agg<64, 1><<<(n + 127) / 128, 256, smem64>>>(W3, b2, n);

    // final: out = (gather HA)*in_norm + b3
    k_agg64_final<<<(n * 16 + 255) / 256, 256>>>(b3, out, n);
}

// round 9
// speedup vs baseline: 1.6138x; 1.2696x over previous
#include <cuda_runtime.h>
#include <cuda_bf16.h>
#include <cstdint>

#define NODES_MAX 100000
#define E_MAX     1600000

// ---------------- device scratch (static, allocation-free) ----------------
__device__ float g_H[(size_t)NODES_MAX * 128];     // pre-aggregation h
__device__ float g_AGG[(size_t)NODES_MAX * 128];   // aggregation result
__device__ float g_out_norm[NODES_MAX];
__device__ float g_in_norm[NODES_MAX];
__device__ int   g_odeg[NODES_MAX];
__device__ int   g_ideg[NODES_MAX];
__device__ int   g_row_beg[NODES_MAX];
__device__ int   g_fill[NODES_MAX];
__device__ int   g_csr_src[E_MAX];
__device__ int   g_alloc_ctr;
__device__ __nv_bfloat16 g_WThi[128 * 128];        // W^T hi part  [n][k]
__device__ __nv_bfloat16 g_WTlo[128 * 128];        // W^T lo part  [n][k]

__device__ __forceinline__ uint32_t smem_u32(const void* p) {
    uint32_t a;
    asm("{ .reg .u64 t; cvta.to.shared.u64 t, %1; cvt.u32.u64 %0, t; }" : "=r"(a) : "l"(p));
    return a;
}

#define LDSM_X4(r0, r1, r2, r3, addr) \
    asm volatile("ldmatrix.sync.aligned.m8n8.x4.shared.b16 {%0,%1,%2,%3}, [%4];" \
        : "=r"(r0), "=r"(r1), "=r"(r2), "=r"(r3) : "r"(addr))

#define MMA_BF16(c, a0, a1, a2, a3, b0, b1) \
    asm volatile("mma.sync.aligned.m16n8k16.row.col.f32.bf16.bf16.f32 " \
        "{%0,%1,%2,%3}, {%4,%5,%6,%7}, {%8,%9}, {%0,%1,%2,%3};" \
        : "+f"((c)[0]), "+f"((c)[1]), "+f"((c)[2]), "+f"((c)[3]) \
        : "r"(a0), "r"(a1), "r"(a2), "r"(a3), "r"(b0), "r"(b1))

// ---------------- degree / norm ----------------
__global__ void k_init_deg(int n) {
    int i = blockIdx.x * blockDim.x + threadIdx.x;
    if (i < n) { g_odeg[i] = 1; g_ideg[i] = 1; }
    if (i == 0) g_alloc_ctr = 0;
}
__global__ void k_count_deg(const int* __restrict__ src, const int* __restrict__ dst, int E) {
    int i = blockIdx.x * blockDim.x + threadIdx.x;
    int st = gridDim.x * blockDim.x;
    for (; i < E; i += st) {
        atomicAdd(&g_odeg[src[i]], 1);
        atomicAdd(&g_ideg[dst[i]], 1);
    }
}
__global__ void k_norms(int n) {
    int i = blockIdx.x * blockDim.x + threadIdx.x;
    if (i < n) {
        g_out_norm[i] = rsqrtf((float)g_odeg[i]);
        g_in_norm[i]  = rsqrtf((float)g_ideg[i]);
    }
}

// ---------------- CSR segment allocation ----------------
__global__ void __launch_bounds__(256)
k_alloc(int n) {
    __shared__ int warp_sums[8];
    __shared__ int block_base;
    int i    = blockIdx.x * 256 + threadIdx.x;
    int lane = threadIdx.x & 31;
    int wid  = threadIdx.x >> 5;
    int deg  = (i < n) ? (g_ideg[i] - 1) : 0;
    int v = deg;
#pragma unroll
    for (int off = 1; off < 32; off <<= 1) {
        int t = __shfl_up_sync(0xffffffffu, v, off);
        if (lane >= off) v += t;
    }
    if (lane == 31) warp_sums[wid] = v;
    __syncthreads();
    if (wid == 0) {
        int s = (lane < 8) ? warp_sums[lane] : 0;
#pragma unroll
        for (int off = 1; off < 8; off <<= 1) {
            int t = __shfl_up_sync(0xffffffffu, s, off);
            if (lane >= off) s += t;
        }
        if (lane < 8) warp_sums[lane] = s;
        if (lane == 7) block_base = atomicAdd(&g_alloc_ctr, s);
    }
    __syncthreads();
    int base = block_base + ((wid > 0) ? warp_sums[wid - 1] : 0) + (v - deg);
    if (i < n) { g_row_beg[i] = base; g_fill[i] = base; }
}

__global__ void k_scatter(const int* __restrict__ src, const int* __restrict__ dst, int E) {
    int i = blockIdx.x * blockDim.x + threadIdx.x;
    int st = gridDim.x * blockDim.x;
    for (; i < E; i += st) {
        int d = dst[i];
        int pos = atomicAdd(&g_fill[d], 1);
        g_csr_src[pos] = src[i];
    }
}

// ---------------- W prep: transpose + bf16 hi/lo split ----------------
template <int DOUT>
__global__ void k_prepW(const float* __restrict__ W) {
    int i = blockIdx.x * blockDim.x + threadIdx.x;   // over DOUT*128
    if (i < DOUT * 128) {
        int nn = i % DOUT;
        int k  = i / DOUT;
        float w = W[k * DOUT + nn];
        __nv_bfloat16 hi = __float2bfloat16(w);
        float rlo = w - __bfloat162float(hi);
        g_WThi[nn * 128 + k] = hi;
        g_WTlo[nn * 128 + k] = __float2bfloat16(rlo);
    }
}

// ---------------- bf16-split HMMA GEMM (mma.sync, baseline PTX) ----------------
// H[64-row tile] = X_eff @ W  via Xhi@Whi + Xlo@Whi + Xhi@Wlo, fp32 accum.
//   MODE 0: X_eff = X*out_norm ;  MODE 1: X_eff = relu(AGG*in_norm + bprev)*out_norm
// smem: A tiles [64][136] bf16 (row stride 272B), B tiles [DOUT][136] bf16.
// Warp w: rows (w>>1)*16..+15, n-tiles (w&1)*NTW..+NTW-1 (NTW = DOUT/16).
template <int DOUT, int MODE>
__global__ void __launch_bounds__(256)
k_gemm_mma(const float* __restrict__ X, const float* __restrict__ bprev, int n)
{
    constexpr int NTW   = DOUT / 16;       // n-tiles per warp
    constexpr int ASTB  = 272;             // row stride bytes (136 bf16)
    constexpr int SM_AHI = 0;
    constexpr int SM_ALO = SM_AHI + 64 * ASTB;
    constexpr int SM_BHI = SM_ALO + 64 * ASTB;
    constexpr int SM_BLO = SM_BHI + DOUT * ASTB;

    extern __shared__ char sm[];
    const uint32_t smb = smem_u32(sm);
    const int t    = threadIdx.x;
    const int lane = t & 31;
    const int wid  = t >> 5;
    const int row0 = blockIdx.x * 64;

    // ---- stage B (W^T hi/lo) : [nn][kg*8..] 16B chunks ----
    for (int g = t; g < DOUT * 16; g += 256) {
        int nn = g >> 4, kg = g & 15;
        char* dhi = sm + SM_BHI + nn * ASTB + kg * 16;
        char* dlo = sm + SM_BLO + nn * ASTB + kg * 16;
        *(uint4*)dhi = *(const uint4*)((const char*)g_WThi + (size_t)g * 16);
        *(uint4*)dlo = *(const uint4*)((const char*)g_WTlo + (size_t)g * 16);
    }

    // ---- stage A (epilogue + hi/lo split) ----
    for (int g = t; g < 64 * 16; g += 256) {
        int r = g >> 4, kg = g & 15;
        int row = row0 + r;
        float x[8];
#pragma unroll
        for (int j = 0; j < 8; j++) x[j] = 0.f;
        if (row < n) {
            if (MODE == 0) {
                float on = g_out_norm[row];
                float4 a = ((const float4*)X)[(size_t)row * 32 + kg * 2];
                float4 b = ((const float4*)X)[(size_t)row * 32 + kg * 2 + 1];
                x[0] = a.x * on; x[1] = a.y * on; x[2] = a.z * on; x[3] = a.w * on;
                x[4] = b.x * on; x[5] = b.y * on; x[6] = b.z * on; x[7] = b.w * on;
            } else {
                float inn = g_in_norm[row];
                float on  = g_out_norm[row];
                float4 a  = ((const float4*)g_AGG)[(size_t)row * 32 + kg * 2];
                float4 b  = ((const float4*)g_AGG)[(size_t)row * 32 + kg * 2 + 1];
                float4 ba = ((const float4*)bprev)[kg * 2];
                float4 bb = ((const float4*)bprev)[kg * 2 + 1];
                x[0] = fmaxf(fmaf(a.x, inn, ba.x), 0.f) * on;
                x[1] = fmaxf(fmaf(a.y, inn, ba.y), 0.f) * on;
                x[2] = fmaxf(fmaf(a.z, inn, ba.z), 0.f) * on;
                x[3] = fmaxf(fmaf(a.w, inn, ba.w), 0.f) * on;
                x[4] = fmaxf(fmaf(b.x, inn, bb.x), 0.f) * on;
                x[5] = fmaxf(fmaf(b.y, inn, bb.y), 0.f) * on;
                x[6] = fmaxf(fmaf(b.z, inn, bb.z), 0.f) * on;
                x[7] = fmaxf(fmaf(b.w, inn, bb.w), 0.f) * on;
            }
        }
        uint32_t hi[4], lo[4];
#pragma unroll
        for (int j = 0; j < 4; j++) {
            __nv_bfloat16 h0 = __float2bfloat16(x[2 * j]);
            __nv_bfloat16 h1 = __float2bfloat16(x[2 * j + 1]);
            __nv_bfloat16 l0 = __float2bfloat16(x[2 * j]     - __bfloat162float(h0));
            __nv_bfloat16 l1 = __float2bfloat16(x[2 * j + 1] - __bfloat162float(h1));
            __nv_bfloat162 ph = __nv_bfloat162(h0, h1);
            __nv_bfloat162 pl = __nv_bfloat162(l0, l1);
            hi[j] = *(uint32_t*)&ph;
            lo[j] = *(uint32_t*)&pl;
        }
        char* dhi = sm + SM_AHI + r * ASTB + kg * 16;
        char* dlo = sm + SM_ALO + r * ASTB + kg * 16;
        *(uint4*)dhi = make_uint4(hi[0], hi[1], hi[2], hi[3]);
        *(uint4*)dlo = make_uint4(lo[0], lo[1], lo[2], lo[3]);
    }
    __syncthreads();

    // ---- compute ----
    const int m0 = (wid >> 1) * 16;               // warp's row base within tile
    const int ch = wid & 1;                       // column half
    const int qd = lane >> 3;                     // ldmatrix quad
    const int ri = lane & 7;                      // row within quad

    float acc[NTW][4];
#pragma unroll
    for (int nt = 0; nt < NTW; nt++) { acc[nt][0] = acc[nt][1] = acc[nt][2] = acc[nt][3] = 0.f; }

    const uint32_t a_off[3] = { smb + SM_AHI, smb + SM_ALO, smb + SM_AHI };
    const uint32_t b_off[3] = { smb + SM_BHI, smb + SM_BHI, smb + SM_BLO };

#pragma unroll
    for (int term = 0; term < 3; term++) {
        // lane's A ldmatrix address pattern: quads = (r0-7,k0)(r8-15,k0)(r0-7,k8)(r8-15,k8)
        uint32_t aAddr = a_off[term] + (uint32_t)(m0 + ri + ((qd & 1) << 3)) * ASTB
                       + (uint32_t)((qd & 2) ? 16 : 0);
        uint32_t bBase = b_off[term] + (uint32_t)(ri + ((qd & 1) << 3)) * ASTB
                       + (uint32_t)((qd & 2) ? 16 : 0);
#pragma unroll
        for (int kk = 0; kk < 8; kk++) {
            uint32_t a0, a1, a2, a3;
            LDSM_X4(a0, a1, a2, a3, aAddr + kk * 32);
#pragma unroll
            for (int p = 0; p < NTW / 2; p++) {
                // B x4 covers n-tiles (2p, 2p+1): quads = (n0-7,k0)(n8-15,k0)(n0-7,k8)(n8-15,k8)
                uint32_t bAddr = bBase + (uint32_t)((ch * NTW + 2 * p) * 8) * ASTB + kk * 32;
                uint32_t b0, b1, b2, b3;
                LDSM_X4(b0, b1, b2, b3, bAddr);
                MMA_BF16(acc[2 * p],     a0, a1, a2, a3, b0, b2);
                MMA_BF16(acc[2 * p + 1], a0, a1, a2, a3, b1, b3);
            }
        }
    }

    // ---- epilogue: c frag rows = m0 + lane/4 (+8), cols = nt*8 + (lane%4)*2 ----
    const int frow = row0 + m0 + (lane >> 2);
    const int fcol = (lane & 3) * 2;
#pragma unroll
    for (int nt = 0; nt < NTW; nt++) {
        int col = (ch * NTW + nt) * 8 + fcol;
        if (frow < n)
            *(float2*)(g_H + (size_t)frow * DOUT + col) = make_float2(acc[nt][0], acc[nt][1]);
        if (frow + 8 < n)
            *(float2*)(g_H + (size_t)(frow + 8) * DOUT + col) = make_float2(acc[nt][2], acc[nt][3]);
    }
}

// ---------------- CSR gather-reduce aggregation (R4-proven) ----------------
__global__ void __launch_bounds__(256)
k_agg128(int n) {
    int w    = (blockIdx.x * blockDim.x + threadIdx.x) >> 5;
    int lane = threadIdx.x & 31;
    if (w >= n) return;
    const float4* H4 = (const float4*)g_H;
    int beg = g_row_beg[w];
    int end = beg + g_ideg[w] - 1;
    float4 acc = H4[(size_t)w * 32 + lane];   // self-loop
    int j = beg;
    for (; j + 1 < end; j += 2) {
        int s0 = __ldg(&g_csr_src[j]);
        int s1 = __ldg(&g_csr_src[j + 1]);
        float4 v0 = H4[(size_t)s0 * 32 + lane];
        float4 v1 = H4[(size_t)s1 * 32 + lane];
        acc.x += v0.x; acc.y += v0.y; acc.z += v0.z; acc.w += v0.w;
        acc.x += v1.x; acc.y += v1.y; acc.z += v1.z; acc.w += v1.w;
    }
    if (j < end) {
        int s0 = __ldg(&g_csr_src[j]);
        float4 v0 = H4[(size_t)s0 * 32 + lane];
        acc.x += v0.x; acc.y += v0.y; acc.z += v0.z; acc.w += v0.w;
    }
    ((float4*)g_AGG)[(size_t)w * 32 + lane] = acc;
}

__global__ void __launch_bounds__(256)
k_agg64_final(const float* __restrict__ b3, float* __restrict__ out, int n) {
    int gt   = blockIdx.x * blockDim.x + threadIdx.x;
    int lane = gt & 31;
    int w    = gt >> 5;
    int sub  = lane >> 4;
    int l16  = lane & 15;
    int node = w * 2 + sub;
    if (node >= n) return;
    const float4* H4 = (const float4*)g_H;
    int beg = g_row_beg[node];
    int end = beg + g_ideg[node] - 1;
    float4 acc = H4[(size_t)node * 16 + l16];  // self-loop
    int j = beg;
    for (; j + 1 < end; j += 2) {
        int s0 = __ldg(&g_csr_src[j]);
        int s1 = __ldg(&g_csr_src[j + 1]);
        float4 v0 = H4[(size_t)s0 * 16 + l16];
        float4 v1 = H4[(size_t)s1 * 16 + l16];
        acc.x += v0.x; acc.y += v0.y; acc.z += v0.z; acc.w += v0.w;
        acc.x += v1.x; acc.y += v1.y; acc.z += v1.z; acc.w += v1.w;
    }
    if (j < end) {
        int s0 = __ldg(&g_csr_src[j]);
        float4 v0 = H4[(size_t)s0 * 16 + l16];
        acc.x += v0.x; acc.y += v0.y; acc.z += v0.z; acc.w += v0.w;
    }
    float inn = g_in_norm[node];
    float4 bb = ((const float4*)b3)[l16];
    float4 o;
    o.x = fmaf(acc.x, inn, bb.x);
    o.y = fmaf(acc.y, inn, bb.y);
    o.z = fmaf(acc.z, inn, bb.z);
    o.w = fmaf(acc.w, inn, bb.w);
    ((float4*)out)[(size_t)node * 16 + l16] = o;
}

// ---------------- launcher ----------------
extern "C" void kernel_launch(void* const* d_in, const int* in_sizes, int n_in,
                              void* d_out, int out_size)
{
    const float* feat = (const float*)d_in[0];
    const int*   src  = (const int*)d_in[1];
    const int*   dst  = (const int*)d_in[2];
    const float* W1   = (const float*)d_in[3];
    const float* b1   = (const float*)d_in[4];
    const float* W2   = (const float*)d_in[5];
    const float* b2   = (const float*)d_in[6];
    const float* W3   = (const float*)d_in[7];
    const float* b3   = (const float*)d_in[8];
    float*       out  = (float*)d_out;

    const int n = in_sizes[0] / 128;   // 100000
    const int E = in_sizes[1];         // 1600000

    const int smem128 = (64 + 64 + 128 + 128) * 272;   // 104,448 B
    const int smem64  = (64 + 64 + 64 + 64) * 272;     //  69,632 B
    cudaFuncSetAttribute((const void*)k_gemm_mma<128, 0>,
                         cudaFuncAttributeMaxDynamicSharedMemorySize, smem128);
    cudaFuncSetAttribute((const void*)k_gemm_mma<128, 1>,
                         cudaFuncAttributeMaxDynamicSharedMemorySize, smem128);
    cudaFuncSetAttribute((const void*)k_gemm_mma<64, 1>,
                         cudaFuncAttributeMaxDynamicSharedMemorySize, smem64);

    // degrees + norms (self-loop via init=1)
    k_init_deg<<<(n + 255) / 256, 256>>>(n);
    k_count_deg<<<1024, 256>>>(src, dst, E);
    k_norms<<<(n + 255) / 256, 256>>>(n);

    // CSR build
    k_alloc<<<(n + 255) / 256, 256>>>(n);
    k_scatter<<<1024, 256>>>(src, dst, E);

    const int gblocks = (n + 63) / 64;   // 1563

    // layer 1
    k_prepW<128><<<(128 * 128 + 255) / 256, 256>>>(W1);
    k_gemm_mma<128, 0><<<gblocks, 256, smem128>>>(feat, nullptr, n);
    k_agg128<<<(n * 32 + 255) / 256, 256>>>(n);

    // layer 2
    k_prepW<128><<<(128 * 128 + 255) / 256, 256>>>(W2);
    k_gemm_mma<128, 1><<<gblocks, 256, smem128>>>(nullptr, b1, n);
    k_agg128<<<(n * 32 + 255) / 256, 256>>>(n);

    // layer 3 (64-wide)
    k_prepW<64><<<(64 * 128 + 255) / 256, 256>>>(W3);
    k_gemm_mma<64, 1><<<gblocks, 256, smem64>>>(nullptr, b2, n);
    k_agg64_final<<<(n * 16 + 255) / 256, 256>>>(b3, out, n);
}

// round 11
// speedup vs baseline: 1.6694x; 1.0345x over previous
#include <cuda_runtime.h>
#include <cuda_bf16.h>
#include <cstdint>

#define NODES_MAX 100000
#define E_MAX     1600000

// ---------------- device scratch (static, allocation-free) ----------------
__device__ float g_H[(size_t)NODES_MAX * 128];     // pre-aggregation h
__device__ float g_AGG[(size_t)NODES_MAX * 128];   // aggregation result
__device__ float g_out_norm[NODES_MAX];
__device__ float g_in_norm[NODES_MAX];
__device__ int   g_odeg[NODES_MAX];
__device__ int   g_ideg[NODES_MAX];
__device__ int   g_row_beg[NODES_MAX];
__device__ int   g_fill[NODES_MAX];
__device__ int   g_csr_src[E_MAX];
__device__ int   g_alloc_ctr;
__device__ __nv_bfloat16 g_W1hi[128 * 128], g_W1lo[128 * 128];   // W^T splits [n][k]
__device__ __nv_bfloat16 g_W2hi[128 * 128], g_W2lo[128 * 128];
__device__ __nv_bfloat16 g_W3hi[64 * 128],  g_W3lo[64 * 128];

__device__ __forceinline__ uint32_t smem_u32(const void* p) {
    uint32_t a;
    asm("{ .reg .u64 t; cvta.to.shared.u64 t, %1; cvt.u32.u64 %0, t; }" : "=r"(a) : "l"(p));
    return a;
}

#define LDSM_X4(r0, r1, r2, r3, addr) \
    asm volatile("ldmatrix.sync.aligned.m8n8.x4.shared.b16 {%0,%1,%2,%3}, [%4];" \
        : "=r"(r0), "=r"(r1), "=r"(r2), "=r"(r3) : "r"(addr))

#define MMA_BF16(c, a0, a1, a2, a3, b0, b1) \
    asm volatile("mma.sync.aligned.m16n8k16.row.col.f32.bf16.bf16.f32 " \
        "{%0,%1,%2,%3}, {%4,%5,%6,%7}, {%8,%9}, {%0,%1,%2,%3};" \
        : "+f"((c)[0]), "+f"((c)[1]), "+f"((c)[2]), "+f"((c)[3]) \
        : "r"(a0), "r"(a1), "r"(a2), "r"(a3), "r"(b0), "r"(b1))

// ---------------- degree / norm ----------------
__global__ void k_init_deg(int n) {
    int i = blockIdx.x * blockDim.x + threadIdx.x;
    if (i < n) { g_odeg[i] = 1; g_ideg[i] = 1; }
    if (i == 0) g_alloc_ctr = 0;
}
__global__ void k_count_deg(const int* __restrict__ src, const int* __restrict__ dst, int E) {
    int i = blockIdx.x * blockDim.x + threadIdx.x;
    int st = gridDim.x * blockDim.x;
    for (; i < E; i += st) {
        atomicAdd(&g_odeg[src[i]], 1);
        atomicAdd(&g_ideg[dst[i]], 1);
    }
}
__global__ void k_norms(int n) {
    int i = blockIdx.x * blockDim.x + threadIdx.x;
    if (i < n) {
        g_out_norm[i] = rsqrtf((float)g_odeg[i]);
        g_in_norm[i]  = rsqrtf((float)g_ideg[i]);
    }
}

// ---------------- CSR segment allocation ----------------
__global__ void __launch_bounds__(256)
k_alloc(int n) {
    __shared__ int warp_sums[8];
    __shared__ int block_base;
    int i    = blockIdx.x * 256 + threadIdx.x;
    int lane = threadIdx.x & 31;
    int wid  = threadIdx.x >> 5;
    int deg  = (i < n) ? (g_ideg[i] - 1) : 0;
    int v = deg;
#pragma unroll
    for (int off = 1; off < 32; off <<= 1) {
        int t = __shfl_up_sync(0xffffffffu, v, off);
        if (lane >= off) v += t;
    }
    if (lane == 31) warp_sums[wid] = v;
    __syncthreads();
    if (wid == 0) {
        int s = (lane < 8) ? warp_sums[lane] : 0;
#pragma unroll
        for (int off = 1; off < 8; off <<= 1) {
            int t = __shfl_up_sync(0xffffffffu, s, off);
            if (lane >= off) s += t;
        }
        if (lane < 8) warp_sums[lane] = s;
        if (lane == 7) block_base = atomicAdd(&g_alloc_ctr, s);
    }
    __syncthreads();
    int base = block_base + ((wid > 0) ? warp_sums[wid - 1] : 0) + (v - deg);
    if (i < n) { g_row_beg[i] = base; g_fill[i] = base; }
}

__global__ void k_scatter(const int* __restrict__ src, const int* __restrict__ dst, int E) {
    int i = blockIdx.x * blockDim.x + threadIdx.x;
    int st = gridDim.x * blockDim.x;
    for (; i < E; i += st) {
        int d = dst[i];
        int pos = atomicAdd(&g_fill[d], 1);
        g_csr_src[pos] = src[i];
    }
}

// ---------------- W prep: transpose + bf16 hi/lo split, all 3 layers at once ----------------
__global__ void k_prepW_all(const float* __restrict__ W1, const float* __restrict__ W2,
                            const float* __restrict__ W3) {
    int i = blockIdx.x * blockDim.x + threadIdx.x;   // 0 .. 40959
    const float* W; __nv_bfloat16 *Hi, *Lo; int dout, idx;
    if (i < 16384)      { W = W1; Hi = g_W1hi; Lo = g_W1lo; dout = 128; idx = i; }
    else if (i < 32768) { W = W2; Hi = g_W2hi; Lo = g_W2lo; dout = 128; idx = i - 16384; }
    else if (i < 40960) { W = W3; Hi = g_W3hi; Lo = g_W3lo; dout = 64;  idx = i - 32768; }
    else return;
    int nn = idx % dout;
    int k  = idx / dout;
    float w = W[k * dout + nn];
    __nv_bfloat16 hi = __float2bfloat16(w);
    float rlo = w - __bfloat162float(hi);
    Hi[nn * 128 + k] = hi;
    Lo[nn * 128 + k] = __float2bfloat16(rlo);
}

// ---------------- bf16-split HMMA GEMM (mma.sync, baseline PTX) ----------------
// 128-row tiles, 512 threads (16 warps: 8 row-groups x 2 col-halves).
// Weight buffers selected by LAYER template param INSIDE device code
// (host code must never take the address of a __device__ symbol).
//   MODE 0: X_eff = X*out_norm ;  MODE 1: X_eff = relu(AGG*in_norm + bprev)*out_norm
template <int DOUT, int MODE, int LAYER>
__global__ void __launch_bounds__(512)
k_gemm_mma(const float* __restrict__ X, const float* __restrict__ bprev, int n)
{
    constexpr int NTW   = DOUT / 16;       // n-tiles per warp
    constexpr int ASTB  = 272;             // row stride bytes (136 bf16)
    constexpr int SM_AHI = 0;
    constexpr int SM_ALO = SM_AHI + 128 * ASTB;
    constexpr int SM_BHI = SM_ALO + 128 * ASTB;
    constexpr int SM_BLO = SM_BHI + DOUT * ASTB;

    const __nv_bfloat16* WHi = (LAYER == 1) ? g_W1hi : (LAYER == 2) ? g_W2hi : g_W3hi;
    const __nv_bfloat16* WLo = (LAYER == 1) ? g_W1lo : (LAYER == 2) ? g_W2lo : g_W3lo;

    extern __shared__ char sm[];
    const uint32_t smb = smem_u32(sm);
    const int t    = threadIdx.x;
    const int lane = t & 31;
    const int wid  = t >> 5;
    const int row0 = blockIdx.x * 128;

    // ---- stage B (W^T hi/lo) ----
    for (int g = t; g < DOUT * 16; g += 512) {
        int nn = g >> 4, kg = g & 15;
        char* dhi = sm + SM_BHI + nn * ASTB + kg * 16;
        char* dlo = sm + SM_BLO + nn * ASTB + kg * 16;
        *(uint4*)dhi = *(const uint4*)((const char*)WHi + (size_t)g * 16);
        *(uint4*)dlo = *(const uint4*)((const char*)WLo + (size_t)g * 16);
    }

    // ---- stage A (epilogue + hi/lo split) ----
    for (int g = t; g < 128 * 16; g += 512) {
        int r = g >> 4, kg = g & 15;
        int row = row0 + r;
        float x[8];
#pragma unroll
        for (int j = 0; j < 8; j++) x[j] = 0.f;
        if (row < n) {
            if (MODE == 0) {
                float on = g_out_norm[row];
                float4 a = ((const float4*)X)[(size_t)row * 32 + kg * 2];
                float4 b = ((const float4*)X)[(size_t)row * 32 + kg * 2 + 1];
                x[0] = a.x * on; x[1] = a.y * on; x[2] = a.z * on; x[3] = a.w * on;
                x[4] = b.x * on; x[5] = b.y * on; x[6] = b.z * on; x[7] = b.w * on;
            } else {
                float inn = g_in_norm[row];
                float on  = g_out_norm[row];
                float4 a  = ((const float4*)g_AGG)[(size_t)row * 32 + kg * 2];
                float4 b  = ((const float4*)g_AGG)[(size_t)row * 32 + kg * 2 + 1];
                float4 ba = ((const float4*)bprev)[kg * 2];
                float4 bb = ((const float4*)bprev)[kg * 2 + 1];
                x[0] = fmaxf(fmaf(a.x, inn, ba.x), 0.f) * on;
                x[1] = fmaxf(fmaf(a.y, inn, ba.y), 0.f) * on;
                x[2] = fmaxf(fmaf(a.z, inn, ba.z), 0.f) * on;
                x[3] = fmaxf(fmaf(a.w, inn, ba.w), 0.f) * on;
                x[4] = fmaxf(fmaf(b.x, inn, bb.x), 0.f) * on;
                x[5] = fmaxf(fmaf(b.y, inn, bb.y), 0.f) * on;
                x[6] = fmaxf(fmaf(b.z, inn, bb.z), 0.f) * on;
                x[7] = fmaxf(fmaf(b.w, inn, bb.w), 0.f) * on;
            }
        }
        uint32_t hi[4], lo[4];
#pragma unroll
        for (int j = 0; j < 4; j++) {
            __nv_bfloat16 h0 = __float2bfloat16(x[2 * j]);
            __nv_bfloat16 h1 = __float2bfloat16(x[2 * j + 1]);
            __nv_bfloat16 l0 = __float2bfloat16(x[2 * j]     - __bfloat162float(h0));
            __nv_bfloat16 l1 = __float2bfloat16(x[2 * j + 1] - __bfloat162float(h1));
            __nv_bfloat162 ph = __nv_bfloat162(h0, h1);
            __nv_bfloat162 pl = __nv_bfloat162(l0, l1);
            hi[j] = *(uint32_t*)&ph;
            lo[j] = *(uint32_t*)&pl;
        }
        char* dhi = sm + SM_AHI + r * ASTB + kg * 16;
        char* dlo = sm + SM_ALO + r * ASTB + kg * 16;
        *(uint4*)dhi = make_uint4(hi[0], hi[1], hi[2], hi[3]);
        *(uint4*)dlo = make_uint4(lo[0], lo[1], lo[2], lo[3]);
    }
    __syncthreads();

    // ---- compute ----
    const int m0 = (wid >> 1) * 16;               // warp's row base within 128-row tile
    const int ch = wid & 1;                       // column half
    const int qd = lane >> 3;                     // ldmatrix quad
    const int ri = lane & 7;                      // row within quad

    float acc[NTW][4];
#pragma unroll
    for (int nt = 0; nt < NTW; nt++) { acc[nt][0] = acc[nt][1] = acc[nt][2] = acc[nt][3] = 0.f; }

    const uint32_t a_off[3] = { smb + SM_AHI, smb + SM_ALO, smb + SM_AHI };
    const uint32_t b_off[3] = { smb + SM_BHI, smb + SM_BHI, smb + SM_BLO };

#pragma unroll
    for (int term = 0; term < 3; term++) {
        uint32_t aAddr = a_off[term] + (uint32_t)(m0 + ri + ((qd & 1) << 3)) * ASTB
                       + (uint32_t)((qd & 2) ? 16 : 0);
        uint32_t bBase = b_off[term] + (uint32_t)(ri + ((qd & 1) << 3)) * ASTB
                       + (uint32_t)((qd & 2) ? 16 : 0);
#pragma unroll
        for (int kk = 0; kk < 8; kk++) {
            uint32_t a0, a1, a2, a3;
            LDSM_X4(a0, a1, a2, a3, aAddr + kk * 32);
#pragma unroll
            for (int p = 0; p < NTW / 2; p++) {
                uint32_t bAddr = bBase + (uint32_t)((ch * NTW + 2 * p) * 8) * ASTB + kk * 32;
                uint32_t b0, b1, b2, b3;
                LDSM_X4(b0, b1, b2, b3, bAddr);
                MMA_BF16(acc[2 * p],     a0, a1, a2, a3, b0, b2);
                MMA_BF16(acc[2 * p + 1], a0, a1, a2, a3, b1, b3);
            }
        }
    }

    // ---- epilogue ----
    const int frow = row0 + m0 + (lane >> 2);
    const int fcol = (lane & 3) * 2;
#pragma unroll
    for (int nt = 0; nt < NTW; nt++) {
        int col = (ch * NTW + nt) * 8 + fcol;
        if (frow < n)
            *(float2*)(g_H + (size_t)frow * DOUT + col) = make_float2(acc[nt][0], acc[nt][1]);
        if (frow + 8 < n)
            *(float2*)(g_H + (size_t)(frow + 8) * DOUT + col) = make_float2(acc[nt][2], acc[nt][3]);
    }
}

// ---------------- CSR gather-reduce aggregation (proven) ----------------
__global__ void __launch_bounds__(256)
k_agg128(int n) {
    int w    = (blockIdx.x * blockDim.x + threadIdx.x) >> 5;
    int lane = threadIdx.x & 31;
    if (w >= n) return;
    const float4* H4 = (const float4*)g_H;
    int beg = g_row_beg[w];
    int end = beg + g_ideg[w] - 1;
    float4 acc = H4[(size_t)w * 32 + lane];   // self-loop
    int j = beg;
    for (; j + 1 < end; j += 2) {
        int s0 = __ldg(&g_csr_src[j]);
        int s1 = __ldg(&g_csr_src[j + 1]);
        float4 v0 = H4[(size_t)s0 * 32 + lane];
        float4 v1 = H4[(size_t)s1 * 32 + lane];
        acc.x += v0.x; acc.y += v0.y; acc.z += v0.z; acc.w += v0.w;
        acc.x += v1.x; acc.y += v1.y; acc.z += v1.z; acc.w += v1.w;
    }
    if (j < end) {
        int s0 = __ldg(&g_csr_src[j]);
        float4 v0 = H4[(size_t)s0 * 32 + lane];
        acc.x += v0.x; acc.y += v0.y; acc.z += v0.z; acc.w += v0.w;
    }
    ((float4*)g_AGG)[(size_t)w * 32 + lane] = acc;
}

__global__ void __launch_bounds__(256)
k_agg64_final(const float* __restrict__ b3, float* __restrict__ out, int n) {
    int gt   = blockIdx.x * blockDim.x + threadIdx.x;
    int lane = gt & 31;
    int w    = gt >> 5;
    int sub  = lane >> 4;
    int l16  = lane & 15;
    int node = w * 2 + sub;
    if (node >= n) return;
    const float4* H4 = (const float4*)g_H;
    int beg = g_row_beg[node];
    int end = beg + g_ideg[node] - 1;
    float4 acc = H4[(size_t)node * 16 + l16];  // self-loop
    int j = beg;
    for (; j + 1 < end; j += 2) {
        int s0 = __ldg(&g_csr_src[j]);
        int s1 = __ldg(&g_csr_src[j + 1]);
        float4 v0 = H4[(size_t)s0 * 16 + l16];
        float4 v1 = H4[(size_t)s1 * 16 + l16];
        acc.x += v0.x; acc.y += v0.y; acc.z += v0.z; acc.w += v0.w;
        acc.x += v1.x; acc.y += v1.y; acc.z += v1.z; acc.w += v1.w;
    }
    if (j < end) {
        int s0 = __ldg(&g_csr_src[j]);
        float4 v0 = H4[(size_t)s0 * 16 + l16];
        acc.x += v0.x; acc.y += v0.y; acc.z += v0.z; acc.w += v0.w;
    }
    float inn = g_in_norm[node];
    float4 bb = ((const float4*)b3)[l16];
    float4 o;
    o.x = fmaf(acc.x, inn, bb.x);
    o.y = fmaf(acc.y, inn, bb.y);
    o.z = fmaf(acc.z, inn, bb.z);
    o.w = fmaf(acc.w, inn, bb.w);
    ((float4*)out)[(size_t)node * 16 + l16] = o;
}

// ---------------- launcher ----------------
extern "C" void kernel_launch(void* const* d_in, const int* in_sizes, int n_in,
                              void* d_out, int out_size)
{
    const float* feat = (const float*)d_in[0];
    const int*   src  = (const int*)d_in[1];
    const int*   dst  = (const int*)d_in[2];
    const float* W1   = (const float*)d_in[3];
    const float* b1   = (const float*)d_in[4];
    const float* W2   = (const float*)d_in[5];
    const float* b2   = (const float*)d_in[6];
    const float* W3   = (const float*)d_in[7];
    const float* b3   = (const float*)d_in[8];
    float*       out  = (float*)d_out;

    const int n = in_sizes[0] / 128;   // 100000
    const int E = in_sizes[1];         // 1600000

    const int smem128 = (128 + 128 + 128 + 128) * 272;   // 139,264 B
    const int smem64  = (128 + 128 + 64 + 64) * 272;     // 104,448 B
    cudaFuncSetAttribute((const void*)k_gemm_mma<128, 0, 1>,
                         cudaFuncAttributeMaxDynamicSharedMemorySize, smem128);
    cudaFuncSetAttribute((const void*)k_gemm_mma<128, 1, 2>,
                         cudaFuncAttributeMaxDynamicSharedMemorySize, smem128);
    cudaFuncSetAttribute((const void*)k_gemm_mma<64, 1, 3>,
                         cudaFuncAttributeMaxDynamicSharedMemorySize, smem64);

    // W prep for all layers (once, up front)
    k_prepW_all<<<(40960 + 255) / 256, 256>>>(W1, W2, W3);

    // degrees + norms (self-loop via init=1)
    k_init_deg<<<(n + 255) / 256, 256>>>(n);
    k_count_deg<<<1024, 256>>>(src, dst, E);
    k_norms<<<(n + 255) / 256, 256>>>(n);

    // CSR build
    k_alloc<<<(n + 255) / 256, 256>>>(n);
    k_scatter<<<1024, 256>>>(src, dst, E);

    const int gblocks = (n + 127) / 128;   // 782

    // layer 1
    k_gemm_mma<128, 0, 1><<<gblocks, 512, smem128>>>(feat, nullptr, n);
    k_agg128<<<(n * 32 + 255) / 256, 256>>>(n);

    // layer 2
    k_gemm_mma<128, 1, 2><<<gblocks, 512, smem128>>>(nullptr, b1, n);
    k_agg128<<<(n * 32 + 255) / 256, 256>>>(n);

    // layer 3 (64-wide)
    k_gemm_mma<64, 1, 3><<<gblocks, 512, smem64>>>(nullptr, b2, n);
    k_agg64_final<<<(n * 16 + 255) / 256, 256>>>(b3, out, n);
}

// round 12
// speedup vs baseline: 1.8464x; 1.1060x over previous
#include <cuda_runtime.h>
#include <cuda_bf16.h>
#include <cuda_fp16.h>
#include <cstdint>

#define NODES_MAX 100000
#define E_MAX     1600000

// ---------------- device scratch (static, allocation-free) ----------------
__device__ __half g_H16[(size_t)NODES_MAX * 128];  // pre-aggregation h (fp16 messages)
__device__ float  g_AGG[(size_t)NODES_MAX * 128];  // aggregation result (fp32)
__device__ float  g_out_norm[NODES_MAX];
__device__ float  g_in_norm[NODES_MAX];
__device__ int    g_odeg[NODES_MAX];
__device__ int    g_ideg[NODES_MAX];
__device__ int    g_row_beg[NODES_MAX];
__device__ int    g_fill[NODES_MAX];
__device__ int    g_csr_src[E_MAX];
__device__ int    g_alloc_ctr;
__device__ __nv_bfloat16 g_W1hi[128 * 128], g_W1lo[128 * 128];   // W^T splits [n][k]
__device__ __nv_bfloat16 g_W2hi[128 * 128], g_W2lo[128 * 128];
__device__ __nv_bfloat16 g_W3hi[64 * 128],  g_W3lo[64 * 128];

__device__ __forceinline__ uint32_t smem_u32(const void* p) {
    uint32_t a;
    asm("{ .reg .u64 t; cvta.to.shared.u64 t, %1; cvt.u32.u64 %0, t; }" : "=r"(a) : "l"(p));
    return a;
}

#define LDSM_X4(r0, r1, r2, r3, addr) \
    asm volatile("ldmatrix.sync.aligned.m8n8.x4.shared.b16 {%0,%1,%2,%3}, [%4];" \
        : "=r"(r0), "=r"(r1), "=r"(r2), "=r"(r3) : "r"(addr))

#define MMA_BF16(c, a0, a1, a2, a3, b0, b1) \
    asm volatile("mma.sync.aligned.m16n8k16.row.col.f32.bf16.bf16.f32 " \
        "{%0,%1,%2,%3}, {%4,%5,%6,%7}, {%8,%9}, {%0,%1,%2,%3};" \
        : "+f"((c)[0]), "+f"((c)[1]), "+f"((c)[2]), "+f"((c)[3]) \
        : "r"(a0), "r"(a1), "r"(a2), "r"(a3), "r"(b0), "r"(b1))

// unpack uint2 (4 fp16) and accumulate into float4
__device__ __forceinline__ void acc_h4(float4& acc, uint2 u) {
    __half2 h0 = *(__half2*)&u.x;
    __half2 h1 = *(__half2*)&u.y;
    float2 f0 = __half22float2(h0);
    float2 f1 = __half22float2(h1);
    acc.x += f0.x; acc.y += f0.y; acc.z += f1.x; acc.w += f1.y;
}

// ---------------- degree / norm ----------------
__global__ void k_init_deg(int n) {
    int i = blockIdx.x * blockDim.x + threadIdx.x;
    if (i < n) { g_odeg[i] = 1; g_ideg[i] = 1; }
    if (i == 0) g_alloc_ctr = 0;
}
__global__ void k_count_deg(const int* __restrict__ src, const int* __restrict__ dst, int E) {
    int i = blockIdx.x * blockDim.x + threadIdx.x;
    int st = gridDim.x * blockDim.x;
    for (; i < E; i += st) {
        atomicAdd(&g_odeg[src[i]], 1);
        atomicAdd(&g_ideg[dst[i]], 1);
    }
}

// ---------------- CSR segment allocation + norms (fused) ----------------
__global__ void __launch_bounds__(256)
k_alloc(int n) {
    __shared__ int warp_sums[8];
    __shared__ int block_base;
    int i    = blockIdx.x * 256 + threadIdx.x;
    int lane = threadIdx.x & 31;
    int wid  = threadIdx.x >> 5;
    int ideg = (i < n) ? g_ideg[i] : 1;
    int deg  = ideg - 1;
    if (i < n) {
        g_out_norm[i] = rsqrtf((float)g_odeg[i]);
        g_in_norm[i]  = rsqrtf((float)ideg);
    }
    int v = deg;
#pragma unroll
    for (int off = 1; off < 32; off <<= 1) {
        int t = __shfl_up_sync(0xffffffffu, v, off);
        if (lane >= off) v += t;
    }
    if (lane == 31) warp_sums[wid] = v;
    __syncthreads();
    if (wid == 0) {
        int s = (lane < 8) ? warp_sums[lane] : 0;
#pragma unroll
        for (int off = 1; off < 8; off <<= 1) {
            int t = __shfl_up_sync(0xffffffffu, s, off);
            if (lane >= off) s += t;
        }
        if (lane < 8) warp_sums[lane] = s;
        if (lane == 7) block_base = atomicAdd(&g_alloc_ctr, s);
    }
    __syncthreads();
    int base = block_base + ((wid > 0) ? warp_sums[wid - 1] : 0) + (v - deg);
    if (i < n) { g_row_beg[i] = base; g_fill[i] = base; }
}

__global__ void k_scatter(const int* __restrict__ src, const int* __restrict__ dst, int E) {
    int i = blockIdx.x * blockDim.x + threadIdx.x;
    int st = gridDim.x * blockDim.x;
    for (; i < E; i += st) {
        int d = dst[i];
        int pos = atomicAdd(&g_fill[d], 1);
        g_csr_src[pos] = src[i];
    }
}

// ---------------- W prep: transpose + bf16 hi/lo split, all 3 layers at once ----------------
__global__ void k_prepW_all(const float* __restrict__ W1, const float* __restrict__ W2,
                            const float* __restrict__ W3) {
    int i = blockIdx.x * blockDim.x + threadIdx.x;   // 0 .. 40959
    const float* W; __nv_bfloat16 *Hi, *Lo; int dout, idx;
    if (i < 16384)      { W = W1; Hi = g_W1hi; Lo = g_W1lo; dout = 128; idx = i; }
    else if (i < 32768) { W = W2; Hi = g_W2hi; Lo = g_W2lo; dout = 128; idx = i - 16384; }
    else if (i < 40960) { W = W3; Hi = g_W3hi; Lo = g_W3lo; dout = 64;  idx = i - 32768; }
    else return;
    int nn = idx % dout;
    int k  = idx / dout;
    float w = W[k * dout + nn];
    __nv_bfloat16 hi = __float2bfloat16(w);
    float rlo = w - __bfloat162float(hi);
    Hi[nn * 128 + k] = hi;
    Lo[nn * 128 + k] = __float2bfloat16(rlo);
}

// ---------------- bf16-split HMMA GEMM (mma.sync, baseline PTX) ----------------
// 128-row tiles, 512 threads (16 warps: 8 row-groups x 2 col-halves).
// Output H written in fp16 (halves aggregation gather traffic).
//   MODE 0: X_eff = X*out_norm ;  MODE 1: X_eff = relu(AGG*in_norm + bprev)*out_norm
template <int DOUT, int MODE, int LAYER>
__global__ void __launch_bounds__(512)
k_gemm_mma(const float* __restrict__ X, const float* __restrict__ bprev, int n)
{
    constexpr int NTW   = DOUT / 16;       // n-tiles per warp
    constexpr int ASTB  = 272;             // row stride bytes (136 bf16)
    constexpr int SM_AHI = 0;
    constexpr int SM_ALO = SM_AHI + 128 * ASTB;
    constexpr int SM_BHI = SM_ALO + 128 * ASTB;
    constexpr int SM_BLO = SM_BHI + DOUT * ASTB;

    const __nv_bfloat16* WHi = (LAYER == 1) ? g_W1hi : (LAYER == 2) ? g_W2hi : g_W3hi;
    const __nv_bfloat16* WLo = (LAYER == 1) ? g_W1lo : (LAYER == 2) ? g_W2lo : g_W3lo;

    extern __shared__ char sm[];
    const uint32_t smb = smem_u32(sm);
    const int t    = threadIdx.x;
    const int lane = t & 31;
    const int wid  = t >> 5;
    const int row0 = blockIdx.x * 128;

    // ---- stage B (W^T hi/lo) ----
    for (int g = t; g < DOUT * 16; g += 512) {
        int nn = g >> 4, kg = g & 15;
        char* dhi = sm + SM_BHI + nn * ASTB + kg * 16;
        char* dlo = sm + SM_BLO + nn * ASTB + kg * 16;
        *(uint4*)dhi = *(const uint4*)((const char*)WHi + (size_t)g * 16);
        *(uint4*)dlo = *(const uint4*)((const char*)WLo + (size_t)g * 16);
    }

    // ---- stage A (epilogue + hi/lo split) ----
    for (int g = t; g < 128 * 16; g += 512) {
        int r = g >> 4, kg = g & 15;
        int row = row0 + r;
        float x[8];
#pragma unroll
        for (int j = 0; j < 8; j++) x[j] = 0.f;
        if (row < n) {
            if (MODE == 0) {
                float on = g_out_norm[row];
                float4 a = ((const float4*)X)[(size_t)row * 32 + kg * 2];
                float4 b = ((const float4*)X)[(size_t)row * 32 + kg * 2 + 1];
                x[0] = a.x * on; x[1] = a.y * on; x[2] = a.z * on; x[3] = a.w * on;
                x[4] = b.x * on; x[5] = b.y * on; x[6] = b.z * on; x[7] = b.w * on;
            } else {
                float inn = g_in_norm[row];
                float on  = g_out_norm[row];
                float4 a  = ((const float4*)g_AGG)[(size_t)row * 32 + kg * 2];
                float4 b  = ((const float4*)g_AGG)[(size_t)row * 32 + kg * 2 + 1];
                float4 ba = ((const float4*)bprev)[kg * 2];
                float4 bb = ((const float4*)bprev)[kg * 2 + 1];
                x[0] = fmaxf(fmaf(a.x, inn, ba.x), 0.f) * on;
                x[1] = fmaxf(fmaf(a.y, inn, ba.y), 0.f) * on;
                x[2] = fmaxf(fmaf(a.z, inn, ba.z), 0.f) * on;
                x[3] = fmaxf(fmaf(a.w, inn, ba.w), 0.f) * on;
                x[4] = fmaxf(fmaf(b.x, inn, bb.x), 0.f) * on;
                x[5] = fmaxf(fmaf(b.y, inn, bb.y), 0.f) * on;
                x[6] = fmaxf(fmaf(b.z, inn, bb.z), 0.f) * on;
                x[7] = fmaxf(fmaf(b.w, inn, bb.w), 0.f) * on;
            }
        }
        uint32_t hi[4], lo[4];
#pragma unroll
        for (int j = 0; j < 4; j++) {
            __nv_bfloat16 h0 = __float2bfloat16(x[2 * j]);
            __nv_bfloat16 h1 = __float2bfloat16(x[2 * j + 1]);
            __nv_bfloat16 l0 = __float2bfloat16(x[2 * j]     - __bfloat162float(h0));
            __nv_bfloat16 l1 = __float2bfloat16(x[2 * j + 1] - __bfloat162float(h1));
            __nv_bfloat162 ph = __nv_bfloat162(h0, h1);
            __nv_bfloat162 pl = __nv_bfloat162(l0, l1);
            hi[j] = *(uint32_t*)&ph;
            lo[j] = *(uint32_t*)&pl;
        }
        char* dhi = sm + SM_AHI + r * ASTB + kg * 16;
        char* dlo = sm + SM_ALO + r * ASTB + kg * 16;
        *(uint4*)dhi = make_uint4(hi[0], hi[1], hi[2], hi[3]);
        *(uint4*)dlo = make_uint4(lo[0], lo[1], lo[2], lo[3]);
    }
    __syncthreads();

    // ---- compute ----
    const int m0 = (wid >> 1) * 16;               // warp's row base within 128-row tile
    const int ch = wid & 1;                       // column half
    const int qd = lane >> 3;                     // ldmatrix quad
    const int ri = lane & 7;                      // row within quad

    float acc[NTW][4];
#pragma unroll
    for (int nt = 0; nt < NTW; nt++) { acc[nt][0] = acc[nt][1] = acc[nt][2] = acc[nt][3] = 0.f; }

    const uint32_t a_off[3] = { smb + SM_AHI, smb + SM_ALO, smb + SM_AHI };
    const uint32_t b_off[3] = { smb + SM_BHI, smb + SM_BHI, smb + SM_BLO };

#pragma unroll
    for (int term = 0; term < 3; term++) {
        uint32_t aAddr = a_off[term] + (uint32_t)(m0 + ri + ((qd & 1) << 3)) * ASTB
                       + (uint32_t)((qd & 2) ? 16 : 0);
        uint32_t bBase = b_off[term] + (uint32_t)(ri + ((qd & 1) << 3)) * ASTB
                       + (uint32_t)((qd & 2) ? 16 : 0);
#pragma unroll
        for (int kk = 0; kk < 8; kk++) {
            uint32_t a0, a1, a2, a3;
            LDSM_X4(a0, a1, a2, a3, aAddr + kk * 32);
#pragma unroll
            for (int p = 0; p < NTW / 2; p++) {
                uint32_t bAddr = bBase + (uint32_t)((ch * NTW + 2 * p) * 8) * ASTB + kk * 32;
                uint32_t b0, b1, b2, b3;
                LDSM_X4(b0, b1, b2, b3, bAddr);
                MMA_BF16(acc[2 * p],     a0, a1, a2, a3, b0, b2);
                MMA_BF16(acc[2 * p + 1], a0, a1, a2, a3, b1, b3);
            }
        }
    }

    // ---- epilogue: write fp16 pairs ----
    const int frow = row0 + m0 + (lane >> 2);
    const int fcol = (lane & 3) * 2;
    uint32_t* H32 = (uint32_t*)g_H16;
#pragma unroll
    for (int nt = 0; nt < NTW; nt++) {
        int col = (ch * NTW + nt) * 8 + fcol;
        if (frow < n) {
            __half2 h = __floats2half2_rn(acc[nt][0], acc[nt][1]);
            H32[((size_t)frow * DOUT + col) >> 1] = *(uint32_t*)&h;
        }
        if (frow + 8 < n) {
            __half2 h = __floats2half2_rn(acc[nt][2], acc[nt][3]);
            H32[((size_t)(frow + 8) * DOUT + col) >> 1] = *(uint32_t*)&h;
        }
    }
}

// ---------------- CSR gather-reduce aggregation (fp16 gather, fp32 accumulate) ----------------
__global__ void __launch_bounds__(256)
k_agg128(int n) {
    int w    = (blockIdx.x * blockDim.x + threadIdx.x) >> 5;
    int lane = threadIdx.x & 31;
    if (w >= n) return;
    const uint2* H2 = (const uint2*)g_H16;    // row = 32 uint2 (128 fp16)
    int beg = g_row_beg[w];
    int end = beg + g_ideg[w] - 1;
    float4 acc = make_float4(0.f, 0.f, 0.f, 0.f);
    acc_h4(acc, H2[(size_t)w * 32 + lane]);   // self-loop
    int j = beg;
    for (; j + 1 < end; j += 2) {
        int s0 = __ldg(&g_csr_src[j]);
        int s1 = __ldg(&g_csr_src[j + 1]);
        uint2 u0 = H2[(size_t)s0 * 32 + lane];
        uint2 u1 = H2[(size_t)s1 * 32 + lane];
        acc_h4(acc, u0);
        acc_h4(acc, u1);
    }
    if (j < end) {
        acc_h4(acc, H2[(size_t)__ldg(&g_csr_src[j]) * 32 + lane]);
    }
    ((float4*)g_AGG)[(size_t)w * 32 + lane] = acc;
}

// 64-wide, final layer: half-warp per dst node; fuses out = acc*in_norm + b3.
__global__ void __launch_bounds__(256)
k_agg64_final(const float* __restrict__ b3, float* __restrict__ out, int n) {
    int gt   = blockIdx.x * blockDim.x + threadIdx.x;
    int lane = gt & 31;
    int w    = gt >> 5;
    int sub  = lane >> 4;
    int l16  = lane & 15;
    int node = w * 2 + sub;
    if (node >= n) return;
    const uint2* H2 = (const uint2*)g_H16;    // row = 16 uint2 (64 fp16)
    int beg = g_row_beg[node];
    int end = beg + g_ideg[node] - 1;
    float4 acc = make_float4(0.f, 0.f, 0.f, 0.f);
    acc_h4(acc, H2[(size_t)node * 16 + l16]); // self-loop
    int j = beg;
    for (; j + 1 < end; j += 2) {
        int s0 = __ldg(&g_csr_src[j]);
        int s1 = __ldg(&g_csr_src[j + 1]);
        uint2 u0 = H2[(size_t)s0 * 16 + l16];
        uint2 u1 = H2[(size_t)s1 * 16 + l16];
        acc_h4(acc, u0);
        acc_h4(acc, u1);
    }
    if (j < end) {
        acc_h4(acc, H2[(size_t)__ldg(&g_csr_src[j]) * 16 + l16]);
    }
    float inn = g_in_norm[node];
    float4 bb = ((const float4*)b3)[l16];
    float4 o;
    o.x = fmaf(acc.x, inn, bb.x);
    o.y = fmaf(acc.y, inn, bb.y);
    o.z = fmaf(acc.z, inn, bb.z);
    o.w = fmaf(acc.w, inn, bb.w);
    ((float4*)out)[(size_t)node * 16 + l16] = o;
}

// ---------------- launcher ----------------
extern "C" void kernel_launch(void* const* d_in, const int* in_sizes, int n_in,
                              void* d_out, int out_size)
{
    const float* feat = (const float*)d_in[0];
    const int*   src  = (const int*)d_in[1];
    const int*   dst  = (const int*)d_in[2];
    const float* W1   = (const float*)d_in[3];
    const float* b1   = (const float*)d_in[4];
    const float* W2   = (const float*)d_in[5];
    const float* b2   = (const float*)d_in[6];
    const float* W3   = (const float*)d_in[7];
    const float* b3   = (const float*)d_in[8];
    float*       out  = (float*)d_out;

    const int n = in_sizes[0] / 128;   // 100000
    const int E = in_sizes[1];         // 1600000

    const int smem128 = (128 + 128 + 128 + 128) * 272;   // 139,264 B
    const int smem64  = (128 + 128 + 64 + 64) * 272;     // 104,448 B
    cudaFuncSetAttribute((const void*)k_gemm_mma<128, 0, 1>,
                         cudaFuncAttributeMaxDynamicSharedMemorySize, smem128);
    cudaFuncSetAttribute((const void*)k_gemm_mma<128, 1, 2>,
                         cudaFuncAttributeMaxDynamicSharedMemorySize, smem128);
    cudaFuncSetAttribute((const void*)k_gemm_mma<64, 1, 3>,
                         cudaFuncAttributeMaxDynamicSharedMemorySize, smem64);

    // W prep for all layers (once, up front)
    k_prepW_all<<<(40960 + 255) / 256, 256>>>(W1, W2, W3);

    // degrees
    k_init_deg<<<(n + 255) / 256, 256>>>(n);
    k_count_deg<<<1024, 256>>>(src, dst, E);

    // CSR build + norms (fused)
    k_alloc<<<(n + 255) / 256, 256>>>(n);
    k_scatter<<<1024, 256>>>(src, dst, E);

    const int gblocks = (n + 127) / 128;   // 782

    // layer 1
    k_gemm_mma<128, 0, 1><<<gblocks, 512, smem128>>>(feat, nullptr, n);
    k_agg128<<<(n * 32 + 255) / 256, 256>>>(n);

    // layer 2
    k_gemm_mma<128, 1, 2><<<gblocks, 512, smem128>>>(nullptr, b1, n);
    k_agg128<<<(n * 32 + 255) / 256, 256>>>(n);

    // layer 3 (64-wide)
    k_gemm_mma<64, 1, 3><<<gblocks, 512, smem64>>>(nullptr, b2, n);
    k_agg64_final<<<(n * 16 + 255) / 256, 256>>>(b3, out, n);
}